// round 2
// baseline (speedup 1.0000x reference)
#include <cuda_runtime.h>
#include <cuda_bf16.h>
#include <cstdint>

// Problem constants
#define N_NODES 50000
#define N_EDGES 800000

// Scratch (allocation-free rule: __device__ globals)
__device__ float g_tmp[N_NODES * 256];  // gemm output (pre-spmm)
__device__ float g_h[N_NODES * 256];    // spmm output / next layer input

// ---------------------------------------------------------------------------
// Tiled fp32 GEMM:  C[M,N] = op(A)[M,K] @ B[K,N]   (op = optional ReLU on A)
// BM=128, BN=128, BK=16, 256 threads, 8x8 micro-tile, double-buffered smem,
// vectorized LDS.128 reads (4 per kk-step feeding 64 FFMA).
// Requires: K % 16 == 0, N % 128 == 0 (true here: K=256, N in {256,128}).
// ---------------------------------------------------------------------------
template <bool RELU_A>
__global__ __launch_bounds__(256) void gemm_kernel(
    const float* __restrict__ A, const float* __restrict__ B,
    float* __restrict__ C, int M, int N, int K)
{
    constexpr int BM = 128, BN = 128, BK = 16;
    constexpr int ASTRIDE = BM + 4;  // pad to kill STS bank conflicts (132*4B, 16B-aligned)

    __shared__ float As[2][BK][ASTRIDE];
    __shared__ float Bs[2][BK][BN];

    const int tid = threadIdx.x;             // 0..255
    const int block_m = blockIdx.y * BM;
    const int block_n = blockIdx.x * BN;

    // micro-tile coords: 16x16 thread grid, each thread owns 8x8
    const int tx = tid & 15;
    const int ty = tid >> 4;
    const int tm = ty * 8;                   // 0..120
    const int tn = tx * 8;

    // A tile load mapping: thread loads 2 float4 along K
    //   row_local = tid/4 (+64), k4 = (tid%4)*4
    const int a_row = tid >> 2;              // 0..63
    const int a_k4  = (tid & 3) * 4;         // 0,4,8,12
    // B tile load mapping: thread loads 2 float4 along N
    //   k = tid/32 (+8), col = (tid%32)*4
    const int b_k   = tid >> 5;              // 0..7
    const int b_col = (tid & 31) * 4;        // 0..124

    const int NT = K / BK;

    float acc[8][8] = {};

    float4 pa[2], pb[2];

    // ---- load tile 0 into buffer 0 ----
    {
        #pragma unroll
        for (int i = 0; i < 2; i++) {
            int gm = block_m + a_row + i * 64;
            float4 v = make_float4(0.f, 0.f, 0.f, 0.f);
            if (gm < M)
                v = *reinterpret_cast<const float4*>(A + (size_t)gm * K + a_k4);
            if (RELU_A) {
                v.x = fmaxf(v.x, 0.f); v.y = fmaxf(v.y, 0.f);
                v.z = fmaxf(v.z, 0.f); v.w = fmaxf(v.w, 0.f);
            }
            As[0][a_k4 + 0][a_row + i * 64] = v.x;
            As[0][a_k4 + 1][a_row + i * 64] = v.y;
            As[0][a_k4 + 2][a_row + i * 64] = v.z;
            As[0][a_k4 + 3][a_row + i * 64] = v.w;
        }
        #pragma unroll
        for (int i = 0; i < 2; i++) {
            int gk = b_k + i * 8;
            float4 v = *reinterpret_cast<const float4*>(B + (size_t)gk * N + block_n + b_col);
            *reinterpret_cast<float4*>(&Bs[0][gk][b_col]) = v;
        }
    }
    __syncthreads();

    for (int t = 0; t < NT; t++) {
        const int buf = t & 1;
        const int k0n = (t + 1) * BK;

        // ---- prefetch next tile into registers ----
        if (t + 1 < NT) {
            #pragma unroll
            for (int i = 0; i < 2; i++) {
                int gm = block_m + a_row + i * 64;
                pa[i] = make_float4(0.f, 0.f, 0.f, 0.f);
                if (gm < M)
                    pa[i] = *reinterpret_cast<const float4*>(A + (size_t)gm * K + k0n + a_k4);
                if (RELU_A) {
                    pa[i].x = fmaxf(pa[i].x, 0.f); pa[i].y = fmaxf(pa[i].y, 0.f);
                    pa[i].z = fmaxf(pa[i].z, 0.f); pa[i].w = fmaxf(pa[i].w, 0.f);
                }
            }
            #pragma unroll
            for (int i = 0; i < 2; i++) {
                int gk = k0n + b_k + i * 8;
                pb[i] = *reinterpret_cast<const float4*>(B + (size_t)gk * N + block_n + b_col);
            }
        }

        // ---- compute on current buffer ----
        #pragma unroll
        for (int kk = 0; kk < BK; kk++) {
            float4 ra0 = *reinterpret_cast<const float4*>(&As[buf][kk][tm]);
            float4 ra1 = *reinterpret_cast<const float4*>(&As[buf][kk][tm + 4]);
            float4 rb0 = *reinterpret_cast<const float4*>(&Bs[buf][kk][tn]);
            float4 rb1 = *reinterpret_cast<const float4*>(&Bs[buf][kk][tn + 4]);
            float ra[8] = {ra0.x, ra0.y, ra0.z, ra0.w, ra1.x, ra1.y, ra1.z, ra1.w};
            float rb[8] = {rb0.x, rb0.y, rb0.z, rb0.w, rb1.x, rb1.y, rb1.z, rb1.w};
            #pragma unroll
            for (int i = 0; i < 8; i++)
                #pragma unroll
                for (int j = 0; j < 8; j++)
                    acc[i][j] = fmaf(ra[i], rb[j], acc[i][j]);
        }

        // ---- store prefetched tile into other buffer ----
        if (t + 1 < NT) {
            const int nbuf = 1 - buf;
            #pragma unroll
            for (int i = 0; i < 2; i++) {
                As[nbuf][a_k4 + 0][a_row + i * 64] = pa[i].x;
                As[nbuf][a_k4 + 1][a_row + i * 64] = pa[i].y;
                As[nbuf][a_k4 + 2][a_row + i * 64] = pa[i].z;
                As[nbuf][a_k4 + 3][a_row + i * 64] = pa[i].w;
            }
            #pragma unroll
            for (int i = 0; i < 2; i++) {
                *reinterpret_cast<float4*>(&Bs[nbuf][b_k + i * 8][b_col]) = pb[i];
            }
            __syncthreads();
        }
    }

    // ---- epilogue ----
    #pragma unroll
    for (int i = 0; i < 8; i++) {
        int gm = block_m + tm + i;
        if (gm < M) {
            float4 v0 = make_float4(acc[i][0], acc[i][1], acc[i][2], acc[i][3]);
            float4 v1 = make_float4(acc[i][4], acc[i][5], acc[i][6], acc[i][7]);
            float* cp = C + (size_t)gm * N + block_n + tn;
            *reinterpret_cast<float4*>(cp)     = v0;
            *reinterpret_cast<float4*>(cp + 4) = v1;
        }
    }
}

// ---------------------------------------------------------------------------
// Init destination rows to bias (broadcast per column)
// ---------------------------------------------------------------------------
__global__ void init_bias_kernel(float* __restrict__ out,
                                 const float* __restrict__ b, int M, int N)
{
    int idx = blockIdx.x * blockDim.x + threadIdx.x;
    int total = M * N / 4;
    if (idx >= total) return;
    int j4 = idx % (N / 4);
    float4 bv = reinterpret_cast<const float4*>(b)[j4];
    reinterpret_cast<float4*>(out)[idx] = bv;
}

// ---------------------------------------------------------------------------
// Edge-parallel SpMM scatter: out[rows[e]] += vals[e] * h[cols[e]]
// One thread per (edge, float4 chunk). red.global.add.v4.f32 (no return).
// ---------------------------------------------------------------------------
template <int K4_SHIFT>
__global__ __launch_bounds__(256) void spmm_kernel(
    const float* __restrict__ h, const float* __restrict__ vals,
    const int* __restrict__ rows, const int* __restrict__ cols,
    float* __restrict__ out)
{
    constexpr int K4 = 1 << K4_SHIFT;
    int idx = blockIdx.x * blockDim.x + threadIdx.x;
    if (idx >= N_EDGES * K4) return;
    int e = idx >> K4_SHIFT;
    int c = idx & (K4 - 1);

    float v = __ldg(&vals[e]);
    int col = __ldg(&cols[e]);
    int row = __ldg(&rows[e]);

    float4 hv = __ldg(reinterpret_cast<const float4*>(h) + ((size_t)col << K4_SHIFT) + c);
    float4 r = make_float4(v * hv.x, v * hv.y, v * hv.z, v * hv.w);

    float* p = out + (((size_t)row << K4_SHIFT) + c) * 4;
    asm volatile("red.global.add.v4.f32 [%0], {%1, %2, %3, %4};"
                 :: "l"(p), "f"(r.x), "f"(r.y), "f"(r.z), "f"(r.w)
                 : "memory");
}

// ---------------------------------------------------------------------------
// Launch
// ---------------------------------------------------------------------------
extern "C" void kernel_launch(void* const* d_in, const int* in_sizes, int n_in,
                              void* d_out, int out_size)
{
    const float* x        = (const float*)d_in[0];
    const float* adj_vals = (const float*)d_in[1];
    const int*   rows     = (const int*)  d_in[2];
    const int*   cols     = (const int*)  d_in[3];
    const float* W1       = (const float*)d_in[4];
    const float* b1       = (const float*)d_in[5];
    const float* W2       = (const float*)d_in[6];
    const float* b2       = (const float*)d_in[7];
    const float* W3       = (const float*)d_in[8];
    const float* b3       = (const float*)d_in[9];
    float* out = (float*)d_out;

    float* tmp; cudaGetSymbolAddress((void**)&tmp, g_tmp);
    float* h;   cudaGetSymbolAddress((void**)&h,   g_h);

    const int M = N_NODES;

    dim3 gemm_block(256);
    dim3 gemm_grid_256(256 / 128, (M + 127) / 128);   // 2 x 391
    dim3 gemm_grid_128(128 / 128, (M + 127) / 128);   // 1 x 391

    int spmm_blocks_256 = (N_EDGES * 64 + 255) / 256;
    int spmm_blocks_128 = (N_EDGES * 32 + 255) / 256;

    int init_blocks_256 = (M * 256 / 4 + 255) / 256;
    int init_blocks_128 = (M * 128 / 4 + 255) / 256;

    // Layer 1: tmp = x @ W1 ; h = b1 ; h += spmm(tmp)   (relu deferred to next A-load)
    gemm_kernel<false><<<gemm_grid_256, gemm_block>>>(x, W1, tmp, M, 256, 256);
    init_bias_kernel<<<init_blocks_256, 256>>>(h, b1, M, 256);
    spmm_kernel<6><<<spmm_blocks_256, 256>>>(tmp, adj_vals, rows, cols, h);

    // Layer 2: tmp = relu(h) @ W2 ; h = b2 ; h += spmm(tmp)
    gemm_kernel<true><<<gemm_grid_256, gemm_block>>>(h, W2, tmp, M, 256, 256);
    init_bias_kernel<<<init_blocks_256, 256>>>(h, b2, M, 256);
    spmm_kernel<6><<<spmm_blocks_256, 256>>>(tmp, adj_vals, rows, cols, h);

    // Layer 3: tmp = relu(h) @ W3 ; out = b3 ; out += spmm(tmp)
    gemm_kernel<true><<<gemm_grid_128, gemm_block>>>(h, W3, tmp, M, 128, 256);
    init_bias_kernel<<<init_blocks_128, 256>>>(out, b3, M, 128);
    spmm_kernel<5><<<spmm_blocks_128, 256>>>(tmp, adj_vals, rows, cols, out);
}

// round 5
// speedup vs baseline: 1.6125x; 1.6125x over previous
#include <cuda_runtime.h>
#include <cuda_bf16.h>
#include <cstdint>

// Problem constants
#define N_NODES 50000
#define N_EDGES 800000

// ---------------------------------------------------------------------------
// Scratch (allocation-free rule: __device__ globals)
// ---------------------------------------------------------------------------
__device__ __align__(16) float g_tmp[N_NODES * 256];   // gemm out (pre-spmm)
__device__ __align__(16) float g_h[N_NODES * 256];     // spmm out / next input
__device__ int   g_cnt[N_NODES];
__device__ int   g_excl[N_NODES];
__device__ int   g_bsum[64];
__device__ int   g_rowptr[N_NODES + 1];
__device__ int   g_wp[N_NODES];
__device__ int   g_cols_s[N_EDGES];
__device__ float g_vals_s[N_EDGES];

// ---------------------------------------------------------------------------
// Tiled fp32 GEMM:  C[M,N] = op(A)[M,K] @ B[K,N]   (op = optional ReLU on A)
// BM=64, BN=64, BK=16, 256 threads, 4x4 micro-tile, vectorized LDS.128.
// ---------------------------------------------------------------------------
template <bool RELU_A>
__global__ __launch_bounds__(256) void gemm_kernel(
    const float* __restrict__ A, const float* __restrict__ B,
    float* __restrict__ C, int M, int N, int K)
{
    constexpr int BM = 64, BN = 64, BK = 16;
    constexpr int ASTRIDE = 68;   // 272B rows: 16B-aligned, 2-way STS conflict only

    __shared__ __align__(16) float As[BK][ASTRIDE];
    __shared__ __align__(16) float Bs[BK][BN];

    const int tid = threadIdx.x;
    const int block_m = blockIdx.y * BM;
    const int block_n = blockIdx.x * BN;

    const int tm = (tid / 16) * 4;
    const int tn = (tid % 16) * 4;

    float acc[4][4] = {};

    const int a_row = tid / 4;             // 0..63 (m)
    const int a_col = (tid % 4) * 4;       // 0..12 (k), 4 elems
    const int b_row = tid / 16;            // 0..15 (k)
    const int b_col = (tid % 16) * 4;      // n, 4 elems

    for (int k0 = 0; k0 < K; k0 += BK) {
        {
            int gm = block_m + a_row;
            float4 v = make_float4(0.f, 0.f, 0.f, 0.f);
            if (gm < M)
                v = *reinterpret_cast<const float4*>(A + (size_t)gm * K + k0 + a_col);
            if (RELU_A) {
                v.x = fmaxf(v.x, 0.f); v.y = fmaxf(v.y, 0.f);
                v.z = fmaxf(v.z, 0.f); v.w = fmaxf(v.w, 0.f);
            }
            As[a_col + 0][a_row] = v.x;
            As[a_col + 1][a_row] = v.y;
            As[a_col + 2][a_row] = v.z;
            As[a_col + 3][a_row] = v.w;
        }
        {
            const float* bp = B + (size_t)(k0 + b_row) * N + block_n + b_col;
            float4 v = *reinterpret_cast<const float4*>(bp);
            *reinterpret_cast<float4*>(&Bs[b_row][b_col]) = v;
        }
        __syncthreads();

        #pragma unroll
        for (int kk = 0; kk < BK; kk++) {
            float4 ra = *reinterpret_cast<const float4*>(&As[kk][tm]);
            float4 rb = *reinterpret_cast<const float4*>(&Bs[kk][tn]);
            float a4[4] = {ra.x, ra.y, ra.z, ra.w};
            float b4[4] = {rb.x, rb.y, rb.z, rb.w};
            #pragma unroll
            for (int i = 0; i < 4; i++)
                #pragma unroll
                for (int j = 0; j < 4; j++)
                    acc[i][j] = fmaf(a4[i], b4[j], acc[i][j]);
        }
        __syncthreads();
    }

    #pragma unroll
    for (int i = 0; i < 4; i++) {
        int gm = block_m + tm + i;
        if (gm < M) {
            float4 v = make_float4(acc[i][0], acc[i][1], acc[i][2], acc[i][3]);
            *reinterpret_cast<float4*>(C + (size_t)gm * N + block_n + tn) = v;
        }
    }
}

// ---------------------------------------------------------------------------
// CSR build: histogram -> 2-level exclusive scan -> scatter
// ---------------------------------------------------------------------------
__global__ void zero_cnt_kernel(int* __restrict__ cnt) {
    int i = blockIdx.x * blockDim.x + threadIdx.x;
    if (i < N_NODES) cnt[i] = 0;
}

__global__ void hist_kernel(const int* __restrict__ rows, int* __restrict__ cnt) {
    int e = blockIdx.x * blockDim.x + threadIdx.x;
    if (e < N_EDGES) atomicAdd(&cnt[rows[e]], 1);
}

__global__ __launch_bounds__(1024) void scan_partial_kernel(
    const int* __restrict__ cnt, int* __restrict__ excl, int* __restrict__ bsum)
{
    __shared__ int s[1024];
    int t = threadIdx.x;
    int i = blockIdx.x * 1024 + t;
    int v = (i < N_NODES) ? cnt[i] : 0;
    s[t] = v;
    __syncthreads();
    #pragma unroll
    for (int o = 1; o < 1024; o <<= 1) {
        int x = (t >= o) ? s[t - o] : 0;
        __syncthreads();
        s[t] += x;
        __syncthreads();
    }
    if (i < N_NODES) excl[i] = s[t] - v;
    if (t == 1023) bsum[blockIdx.x] = s[1023];
}

__global__ void scan_bsum_kernel(int* __restrict__ bsum, int nb) {
    if (threadIdx.x == 0 && blockIdx.x == 0) {
        int run = 0;
        for (int b = 0; b < nb; b++) { int v = bsum[b]; bsum[b] = run; run += v; }
    }
}

__global__ void scan_add_kernel(const int* __restrict__ excl, const int* __restrict__ bsum,
                                int* __restrict__ rowptr, int* __restrict__ wp)
{
    int i = blockIdx.x * blockDim.x + threadIdx.x;
    if (i < N_NODES) {
        int v = excl[i] + bsum[i >> 10];
        rowptr[i] = v;
        wp[i] = v;
    }
    if (i == 0) rowptr[N_NODES] = N_EDGES;
}

__global__ void scatter_edges_kernel(
    const int* __restrict__ rows, const int* __restrict__ cols,
    const float* __restrict__ vals, int* __restrict__ wp,
    int* __restrict__ col_s, float* __restrict__ val_s)
{
    int e = blockIdx.x * blockDim.x + threadIdx.x;
    if (e >= N_EDGES) return;
    int p = atomicAdd(&wp[rows[e]], 1);
    col_s[p] = cols[e];
    val_s[p] = vals[e];
}

// ---------------------------------------------------------------------------
// CSR SpMM, warp per row:  out[r] = bias + sum_j val_s[j] * h[col_s[j]]
// NF = 256 or 128 feats; lane handles NF/128 float4 chunks.
// ---------------------------------------------------------------------------
template <int NF>
__global__ __launch_bounds__(256) void csr_spmm_kernel(
    const float* __restrict__ h, const float* __restrict__ val_s,
    const int* __restrict__ col_s, const int* __restrict__ rowptr,
    const float* __restrict__ bias, float* __restrict__ out)
{
    constexpr int U = NF / 128;   // float4 chunks per lane
    int w = (blockIdx.x * 256 + threadIdx.x) >> 5;
    int lane = threadIdx.x & 31;
    if (w >= N_NODES) return;

    int s = rowptr[w];
    int e = rowptr[w + 1];

    float4 acc[U];
    #pragma unroll
    for (int u = 0; u < U; u++)
        acc[u] = __ldg((const float4*)bias + u * 32 + lane);

    int j = s;
    for (; j + 2 <= e; j += 2) {
        float v0 = __ldg(&val_s[j]);
        float v1 = __ldg(&val_s[j + 1]);
        int   c0 = __ldg(&col_s[j]);
        int   c1 = __ldg(&col_s[j + 1]);
        const float4* hp0 = (const float4*)(h + (size_t)c0 * NF);
        const float4* hp1 = (const float4*)(h + (size_t)c1 * NF);
        float4 hv0[U], hv1[U];
        #pragma unroll
        for (int u = 0; u < U; u++) hv0[u] = __ldg(hp0 + u * 32 + lane);
        #pragma unroll
        for (int u = 0; u < U; u++) hv1[u] = __ldg(hp1 + u * 32 + lane);
        #pragma unroll
        for (int u = 0; u < U; u++) {
            acc[u].x = fmaf(v0, hv0[u].x, acc[u].x);
            acc[u].y = fmaf(v0, hv0[u].y, acc[u].y);
            acc[u].z = fmaf(v0, hv0[u].z, acc[u].z);
            acc[u].w = fmaf(v0, hv0[u].w, acc[u].w);
        }
        #pragma unroll
        for (int u = 0; u < U; u++) {
            acc[u].x = fmaf(v1, hv1[u].x, acc[u].x);
            acc[u].y = fmaf(v1, hv1[u].y, acc[u].y);
            acc[u].z = fmaf(v1, hv1[u].z, acc[u].z);
            acc[u].w = fmaf(v1, hv1[u].w, acc[u].w);
        }
    }
    if (j < e) {
        float v0 = __ldg(&val_s[j]);
        int   c0 = __ldg(&col_s[j]);
        const float4* hp0 = (const float4*)(h + (size_t)c0 * NF);
        #pragma unroll
        for (int u = 0; u < U; u++) {
            float4 hv = __ldg(hp0 + u * 32 + lane);
            acc[u].x = fmaf(v0, hv.x, acc[u].x);
            acc[u].y = fmaf(v0, hv.y, acc[u].y);
            acc[u].z = fmaf(v0, hv.z, acc[u].z);
            acc[u].w = fmaf(v0, hv.w, acc[u].w);
        }
    }

    float4* op = (float4*)(out + (size_t)w * NF);
    #pragma unroll
    for (int u = 0; u < U; u++)
        op[u * 32 + lane] = acc[u];
}

// ---------------------------------------------------------------------------
// Launch
// ---------------------------------------------------------------------------
extern "C" void kernel_launch(void* const* d_in, const int* in_sizes, int n_in,
                              void* d_out, int out_size)
{
    const float* x        = (const float*)d_in[0];
    const float* adj_vals = (const float*)d_in[1];
    const int*   rows     = (const int*)  d_in[2];
    const int*   cols     = (const int*)  d_in[3];
    const float* W1       = (const float*)d_in[4];
    const float* b1       = (const float*)d_in[5];
    const float* W2       = (const float*)d_in[6];
    const float* b2       = (const float*)d_in[7];
    const float* W3       = (const float*)d_in[8];
    const float* b3       = (const float*)d_in[9];
    float* out = (float*)d_out;

    float* tmp;    cudaGetSymbolAddress((void**)&tmp,    g_tmp);
    float* h;      cudaGetSymbolAddress((void**)&h,      g_h);
    int*   cnt;    cudaGetSymbolAddress((void**)&cnt,    g_cnt);
    int*   excl;   cudaGetSymbolAddress((void**)&excl,   g_excl);
    int*   bsum;   cudaGetSymbolAddress((void**)&bsum,   g_bsum);
    int*   rowptr; cudaGetSymbolAddress((void**)&rowptr, g_rowptr);
    int*   wp;     cudaGetSymbolAddress((void**)&wp,     g_wp);
    int*   col_s;  cudaGetSymbolAddress((void**)&col_s,  g_cols_s);
    float* val_s;  cudaGetSymbolAddress((void**)&val_s,  g_vals_s);

    const int M = N_NODES;
    const int nscan = (N_NODES + 1023) / 1024;   // 49

    // ---- CSR build ----
    zero_cnt_kernel<<<(N_NODES + 255) / 256, 256>>>(cnt);
    hist_kernel<<<(N_EDGES + 255) / 256, 256>>>(rows, cnt);
    scan_partial_kernel<<<nscan, 1024>>>(cnt, excl, bsum);
    scan_bsum_kernel<<<1, 32>>>(bsum, nscan);
    scan_add_kernel<<<(N_NODES + 255) / 256, 256>>>(excl, bsum, rowptr, wp);
    scatter_edges_kernel<<<(N_EDGES + 255) / 256, 256>>>(rows, cols, adj_vals, wp, col_s, val_s);

    dim3 gemm_block(256);
    dim3 gemm_grid_256((256 + 63) / 64, (M + 63) / 64);
    dim3 gemm_grid_128((128 + 63) / 64, (M + 63) / 64);

    const int spmm_blocks = (N_NODES * 32 + 255) / 256;   // warp per row

    // Layer 1: tmp = x @ W1 ; h = b1 + spmm(tmp)
    gemm_kernel<false><<<gemm_grid_256, gemm_block>>>(x, W1, tmp, M, 256, 256);
    csr_spmm_kernel<256><<<spmm_blocks, 256>>>(tmp, val_s, col_s, rowptr, b1, h);

    // Layer 2: tmp = relu(h) @ W2 ; h = b2 + spmm(tmp)
    gemm_kernel<true><<<gemm_grid_256, gemm_block>>>(h, W2, tmp, M, 256, 256);
    csr_spmm_kernel<256><<<spmm_blocks, 256>>>(tmp, val_s, col_s, rowptr, b2, h);

    // Layer 3: tmp = relu(h) @ W3 ; out = b3 + spmm(tmp)
    gemm_kernel<true><<<gemm_grid_128, gemm_block>>>(h, W3, tmp, M, 128, 256);
    csr_spmm_kernel<128><<<spmm_blocks, 256>>>(tmp, val_s, col_s, rowptr, b3, out);
}

// round 6
// speedup vs baseline: 2.0255x; 1.2561x over previous
#include <cuda_runtime.h>
#include <cuda_bf16.h>
#include <cstdint>

// Problem constants
#define N_NODES 50000
#define N_EDGES 800000

// ---------------------------------------------------------------------------
// Scratch (allocation-free rule: __device__ globals)
// ---------------------------------------------------------------------------
__device__ __align__(16) float g_tmp[N_NODES * 256];                     // gemm out fp32
__device__ __align__(16) __nv_bfloat16 g_aspA[(size_t)N_NODES * 512];    // [Ah|Al]
__device__ __align__(16) __nv_bfloat16 g_aspB[(size_t)N_NODES * 512];    // [Ah|Al]
__device__ __align__(16) __nv_bfloat16 g_wsplit[256 * 768];              // [N,768] = [Wh|Wh|Wl]
__device__ int   g_cnt[N_NODES];
__device__ int   g_excl[N_NODES];
__device__ int   g_bsum[64];
__device__ int   g_rowptr[N_NODES + 1];
__device__ int   g_wp[N_NODES];
__device__ int   g_cols_s[N_EDGES];
__device__ float g_vals_s[N_EDGES];

// ---------------------------------------------------------------------------
// bf16 mma.sync GEMM:  C[M,N] = A'[M,768eff] @ B'[N,768]^T  (fp32 accum)
// A' stored [M,512] ([Ah|Al]); k-chunks 16..23 re-read the hi half.
// CTA 128x128, 8 warps, warp tile 64x32, m16n8k16 fragments via direct LDS.32.
// ---------------------------------------------------------------------------
__device__ __forceinline__ void mma16816(float* c, const uint32_t* a, const uint32_t* b) {
    asm volatile(
        "mma.sync.aligned.m16n8k16.row.col.f32.bf16.bf16.f32 "
        "{%0,%1,%2,%3}, {%4,%5,%6,%7}, {%8,%9}, {%0,%1,%2,%3};"
        : "+f"(c[0]), "+f"(c[1]), "+f"(c[2]), "+f"(c[3])
        : "r"(a[0]), "r"(a[1]), "r"(a[2]), "r"(a[3]), "r"(b[0]), "r"(b[1]));
}

__global__ __launch_bounds__(256) void gemm_mma(
    const __nv_bfloat16* __restrict__ A,   // [M,512]
    const __nv_bfloat16* __restrict__ Bt,  // [N,768] n-major
    float* __restrict__ C, int M, int N)
{
    constexpr int STRIDE = 40;             // bf16 per smem row (80B: 16B-mult, conflict-free)
    __shared__ __align__(16) __nv_bfloat16 As[128 * STRIDE];
    __shared__ __align__(16) __nv_bfloat16 Bs[128 * STRIDE];

    const int tid   = threadIdx.x;
    const int warp  = tid >> 5;
    const int lane  = tid & 31;
    const int group = lane >> 2;           // 0..7
    const int tig   = lane & 3;            // 0..3

    const int block_m = blockIdx.y * 128;
    const int block_n = blockIdx.x * 128;
    const int wm = (warp & 1) * 64;
    const int wn = (warp >> 1) * 32;

    float acc[4][4][4];
    #pragma unroll
    for (int i = 0; i < 4; i++)
        #pragma unroll
        for (int j = 0; j < 4; j++)
            #pragma unroll
            for (int r = 0; r < 4; r++) acc[i][j][r] = 0.f;

    const int ld_row = tid >> 2;           // 0..63 (x2 halves below)
    const int ld_c   = tid & 3;            // uint4 slot (8 bf16)

    for (int t = 0; t < 24; t++) {
        const int ak0 = (t < 16) ? t * 32 : (t - 16) * 32;  // re-read hi for 16..23
        const int bk0 = t * 32;

        // A tile 128x32
        #pragma unroll
        for (int i = 0; i < 2; i++) {
            int row = ld_row + i * 64;
            int gm = block_m + row;
            uint4 v = make_uint4(0u, 0u, 0u, 0u);
            if (gm < M)
                v = *(const uint4*)(A + (size_t)gm * 512 + ak0 + ld_c * 8);
            *(uint4*)(As + row * STRIDE + ld_c * 8) = v;
        }
        // B tile 128x32 (rows = n)
        #pragma unroll
        for (int i = 0; i < 2; i++) {
            int row = ld_row + i * 64;
            uint4 v = *(const uint4*)(Bt + (size_t)(block_n + row) * 768 + bk0 + ld_c * 8);
            *(uint4*)(Bs + row * STRIDE + ld_c * 8) = v;
        }
        __syncthreads();

        #pragma unroll
        for (int k16 = 0; k16 < 2; k16++) {
            const int k0 = k16 * 16;
            uint32_t af[4][4], bfr[4][2];
            #pragma unroll
            for (int mt = 0; mt < 4; mt++) {
                const __nv_bfloat16* base = As + (wm + mt * 16 + group) * STRIDE + k0 + tig * 2;
                af[mt][0] = *(const uint32_t*)(base);
                af[mt][1] = *(const uint32_t*)(base + 8 * STRIDE);
                af[mt][2] = *(const uint32_t*)(base + 8);
                af[mt][3] = *(const uint32_t*)(base + 8 * STRIDE + 8);
            }
            #pragma unroll
            for (int nt = 0; nt < 4; nt++) {
                const __nv_bfloat16* base = Bs + (wn + nt * 8 + group) * STRIDE + k0 + tig * 2;
                bfr[nt][0] = *(const uint32_t*)(base);
                bfr[nt][1] = *(const uint32_t*)(base + 8);
            }
            #pragma unroll
            for (int mt = 0; mt < 4; mt++)
                #pragma unroll
                for (int nt = 0; nt < 4; nt++)
                    mma16816(acc[mt][nt], af[mt], bfr[nt]);
        }
        __syncthreads();
    }

    // epilogue
    #pragma unroll
    for (int mt = 0; mt < 4; mt++) {
        #pragma unroll
        for (int nt = 0; nt < 4; nt++) {
            int gr = block_m + wm + mt * 16 + group;
            int gc = block_n + wn + nt * 8 + tig * 2;
            if (gr < M)
                *(float2*)(C + (size_t)gr * N + gc) =
                    make_float2(acc[mt][nt][0], acc[mt][nt][1]);
            if (gr + 8 < M)
                *(float2*)(C + (size_t)(gr + 8) * N + gc) =
                    make_float2(acc[mt][nt][2], acc[mt][nt][3]);
        }
    }
}

// ---------------------------------------------------------------------------
// Split fp32 activations -> [Ah|Al] bf16 rows of 512 (layer-1 input only)
// ---------------------------------------------------------------------------
__global__ __launch_bounds__(256) void split_act(
    const float* __restrict__ A, __nv_bfloat16* __restrict__ out, int M)
{
    int idx = blockIdx.x * blockDim.x + threadIdx.x;   // over M*64 float4s
    if (idx >= M * 64) return;
    int m = idx >> 6, c4 = idx & 63;
    float4 v = *((const float4*)(A + (size_t)m * 256) + c4);
    __nv_bfloat16 h0 = __float2bfloat16(v.x), h1 = __float2bfloat16(v.y);
    __nv_bfloat16 h2 = __float2bfloat16(v.z), h3 = __float2bfloat16(v.w);
    __nv_bfloat16 l0 = __float2bfloat16(v.x - __bfloat162float(h0));
    __nv_bfloat16 l1 = __float2bfloat16(v.y - __bfloat162float(h1));
    __nv_bfloat16 l2 = __float2bfloat16(v.z - __bfloat162float(h2));
    __nv_bfloat16 l3 = __float2bfloat16(v.w - __bfloat162float(h3));
    __nv_bfloat16* row = out + (size_t)m * 512;
    __nv_bfloat162* hp = (__nv_bfloat162*)(row) + c4 * 2;
    __nv_bfloat162* lp = (__nv_bfloat162*)(row + 256) + c4 * 2;
    hp[0] = __nv_bfloat162(h0, h1); hp[1] = __nv_bfloat162(h2, h3);
    lp[0] = __nv_bfloat162(l0, l1); lp[1] = __nv_bfloat162(l2, l3);
}

// ---------------------------------------------------------------------------
// Split fp32 weights W[256,N] -> B'[N,768] bf16 ([Wh|Wh|Wl] along k)
// ---------------------------------------------------------------------------
__global__ __launch_bounds__(256) void split_w(
    const float* __restrict__ W, __nv_bfloat16* __restrict__ out, int N)
{
    int idx = blockIdx.x * blockDim.x + threadIdx.x;
    if (idx >= N * 256) return;
    int n = idx >> 8, k = idx & 255;
    float w = W[(size_t)k * N + n];
    __nv_bfloat16 hi = __float2bfloat16(w);
    __nv_bfloat16 lo = __float2bfloat16(w - __bfloat162float(hi));
    __nv_bfloat16* row = out + (size_t)n * 768;
    row[k] = hi; row[256 + k] = hi; row[512 + k] = lo;
}

// ---------------------------------------------------------------------------
// CSR build: histogram -> 2-level exclusive scan -> scatter
// ---------------------------------------------------------------------------
__global__ void zero_cnt_kernel(int* __restrict__ cnt) {
    int i = blockIdx.x * blockDim.x + threadIdx.x;
    if (i < N_NODES) cnt[i] = 0;
}

__global__ void hist_kernel(const int* __restrict__ rows, int* __restrict__ cnt) {
    int e = blockIdx.x * blockDim.x + threadIdx.x;
    if (e < N_EDGES) atomicAdd(&cnt[rows[e]], 1);
}

__global__ __launch_bounds__(1024) void scan_partial_kernel(
    const int* __restrict__ cnt, int* __restrict__ excl, int* __restrict__ bsum)
{
    __shared__ int s[1024];
    int t = threadIdx.x;
    int i = blockIdx.x * 1024 + t;
    int v = (i < N_NODES) ? cnt[i] : 0;
    s[t] = v;
    __syncthreads();
    #pragma unroll
    for (int o = 1; o < 1024; o <<= 1) {
        int x = (t >= o) ? s[t - o] : 0;
        __syncthreads();
        s[t] += x;
        __syncthreads();
    }
    if (i < N_NODES) excl[i] = s[t] - v;
    if (t == 1023) bsum[blockIdx.x] = s[1023];
}

__global__ void scan_bsum_kernel(int* __restrict__ bsum, int nb) {
    if (threadIdx.x == 0 && blockIdx.x == 0) {
        int run = 0;
        for (int b = 0; b < nb; b++) { int v = bsum[b]; bsum[b] = run; run += v; }
    }
}

__global__ void scan_add_kernel(const int* __restrict__ excl, const int* __restrict__ bsum,
                                int* __restrict__ rowptr, int* __restrict__ wp)
{
    int i = blockIdx.x * blockDim.x + threadIdx.x;
    if (i < N_NODES) {
        int v = excl[i] + bsum[i >> 10];
        rowptr[i] = v;
        wp[i] = v;
    }
    if (i == 0) rowptr[N_NODES] = N_EDGES;
}

__global__ void scatter_edges_kernel(
    const int* __restrict__ rows, const int* __restrict__ cols,
    const float* __restrict__ vals, int* __restrict__ wp,
    int* __restrict__ col_s, float* __restrict__ val_s)
{
    int e = blockIdx.x * blockDim.x + threadIdx.x;
    if (e >= N_EDGES) return;
    int p = atomicAdd(&wp[rows[e]], 1);
    col_s[p] = cols[e];
    val_s[p] = vals[e];
}

// ---------------------------------------------------------------------------
// CSR SpMM, warp per row:  acc = bias + sum_j val * h[col]
// SPLIT_OUT=1: write relu(acc) as bf16 hi/lo split rows of 512 (next gemm input)
// SPLIT_OUT=0: write fp32 rows of NF (final output)
// ---------------------------------------------------------------------------
template <int NF, int SPLIT_OUT>
__global__ __launch_bounds__(256) void csr_spmm_kernel(
    const float* __restrict__ h, const float* __restrict__ val_s,
    const int* __restrict__ col_s, const int* __restrict__ rowptr,
    const float* __restrict__ bias, void* __restrict__ outv)
{
    constexpr int U = NF / 128;   // float4 chunks per lane
    int w = (blockIdx.x * 256 + threadIdx.x) >> 5;
    int lane = threadIdx.x & 31;
    if (w >= N_NODES) return;

    int s = rowptr[w];
    int e = rowptr[w + 1];

    float4 acc[U];
    #pragma unroll
    for (int u = 0; u < U; u++)
        acc[u] = __ldg((const float4*)bias + u * 32 + lane);

    int j = s;
    for (; j + 2 <= e; j += 2) {
        float v0 = __ldg(&val_s[j]);
        float v1 = __ldg(&val_s[j + 1]);
        int   c0 = __ldg(&col_s[j]);
        int   c1 = __ldg(&col_s[j + 1]);
        const float4* hp0 = (const float4*)(h + (size_t)c0 * NF);
        const float4* hp1 = (const float4*)(h + (size_t)c1 * NF);
        float4 hv0[U], hv1[U];
        #pragma unroll
        for (int u = 0; u < U; u++) hv0[u] = __ldg(hp0 + u * 32 + lane);
        #pragma unroll
        for (int u = 0; u < U; u++) hv1[u] = __ldg(hp1 + u * 32 + lane);
        #pragma unroll
        for (int u = 0; u < U; u++) {
            acc[u].x = fmaf(v0, hv0[u].x, acc[u].x);
            acc[u].y = fmaf(v0, hv0[u].y, acc[u].y);
            acc[u].z = fmaf(v0, hv0[u].z, acc[u].z);
            acc[u].w = fmaf(v0, hv0[u].w, acc[u].w);
        }
        #pragma unroll
        for (int u = 0; u < U; u++) {
            acc[u].x = fmaf(v1, hv1[u].x, acc[u].x);
            acc[u].y = fmaf(v1, hv1[u].y, acc[u].y);
            acc[u].z = fmaf(v1, hv1[u].z, acc[u].z);
            acc[u].w = fmaf(v1, hv1[u].w, acc[u].w);
        }
    }
    if (j < e) {
        float v0 = __ldg(&val_s[j]);
        int   c0 = __ldg(&col_s[j]);
        const float4* hp0 = (const float4*)(h + (size_t)c0 * NF);
        #pragma unroll
        for (int u = 0; u < U; u++) {
            float4 hv = __ldg(hp0 + u * 32 + lane);
            acc[u].x = fmaf(v0, hv.x, acc[u].x);
            acc[u].y = fmaf(v0, hv.y, acc[u].y);
            acc[u].z = fmaf(v0, hv.z, acc[u].z);
            acc[u].w = fmaf(v0, hv.w, acc[u].w);
        }
    }

    if (SPLIT_OUT) {
        // relu, then split into [Ah|Al] bf16 rows of 512
        __nv_bfloat16* row = (__nv_bfloat16*)outv + (size_t)w * 512;
        #pragma unroll
        for (int u = 0; u < U; u++) {
            float4 a = acc[u];
            a.x = fmaxf(a.x, 0.f); a.y = fmaxf(a.y, 0.f);
            a.z = fmaxf(a.z, 0.f); a.w = fmaxf(a.w, 0.f);
            __nv_bfloat16 h0 = __float2bfloat16(a.x), h1 = __float2bfloat16(a.y);
            __nv_bfloat16 h2 = __float2bfloat16(a.z), h3 = __float2bfloat16(a.w);
            __nv_bfloat16 l0 = __float2bfloat16(a.x - __bfloat162float(h0));
            __nv_bfloat16 l1 = __float2bfloat16(a.y - __bfloat162float(h1));
            __nv_bfloat16 l2 = __float2bfloat16(a.z - __bfloat162float(h2));
            __nv_bfloat16 l3 = __float2bfloat16(a.w - __bfloat162float(h3));
            int fi = u * 32 + lane;   // float4 index
            __nv_bfloat162* hp = (__nv_bfloat162*)(row) + fi * 2;
            __nv_bfloat162* lp = (__nv_bfloat162*)(row + 256) + fi * 2;
            hp[0] = __nv_bfloat162(h0, h1); hp[1] = __nv_bfloat162(h2, h3);
            lp[0] = __nv_bfloat162(l0, l1); lp[1] = __nv_bfloat162(l2, l3);
        }
    } else {
        float4* op = (float4*)((float*)outv + (size_t)w * NF);
        #pragma unroll
        for (int u = 0; u < U; u++)
            op[u * 32 + lane] = acc[u];
    }
}

// ---------------------------------------------------------------------------
// Launch
// ---------------------------------------------------------------------------
extern "C" void kernel_launch(void* const* d_in, const int* in_sizes, int n_in,
                              void* d_out, int out_size)
{
    const float* x        = (const float*)d_in[0];
    const float* adj_vals = (const float*)d_in[1];
    const int*   rows     = (const int*)  d_in[2];
    const int*   cols     = (const int*)  d_in[3];
    const float* W1       = (const float*)d_in[4];
    const float* b1       = (const float*)d_in[5];
    const float* W2       = (const float*)d_in[6];
    const float* b2       = (const float*)d_in[7];
    const float* W3       = (const float*)d_in[8];
    const float* b3       = (const float*)d_in[9];
    float* out = (float*)d_out;

    float* tmp;    cudaGetSymbolAddress((void**)&tmp,    g_tmp);
    __nv_bfloat16* aspA; cudaGetSymbolAddress((void**)&aspA, g_aspA);
    __nv_bfloat16* aspB; cudaGetSymbolAddress((void**)&aspB, g_aspB);
    __nv_bfloat16* wsp;  cudaGetSymbolAddress((void**)&wsp,  g_wsplit);
    int*   cnt;    cudaGetSymbolAddress((void**)&cnt,    g_cnt);
    int*   excl;   cudaGetSymbolAddress((void**)&excl,   g_excl);
    int*   bsum;   cudaGetSymbolAddress((void**)&bsum,   g_bsum);
    int*   rowptr; cudaGetSymbolAddress((void**)&rowptr, g_rowptr);
    int*   wp;     cudaGetSymbolAddress((void**)&wp,     g_wp);
    int*   col_s;  cudaGetSymbolAddress((void**)&col_s,  g_cols_s);
    float* val_s;  cudaGetSymbolAddress((void**)&val_s,  g_vals_s);

    const int M = N_NODES;
    const int nscan = (N_NODES + 1023) / 1024;   // 49

    // ---- CSR build ----
    zero_cnt_kernel<<<(N_NODES + 255) / 256, 256>>>(cnt);
    hist_kernel<<<(N_EDGES + 255) / 256, 256>>>(rows, cnt);
    scan_partial_kernel<<<nscan, 1024>>>(cnt, excl, bsum);
    scan_bsum_kernel<<<1, 32>>>(bsum, nscan);
    scan_add_kernel<<<(N_NODES + 255) / 256, 256>>>(excl, bsum, rowptr, wp);
    scatter_edges_kernel<<<(N_EDGES + 255) / 256, 256>>>(rows, cols, adj_vals, wp, col_s, val_s);

    const int gemm_gm = (M + 127) / 128;                  // 391
    dim3 gemm_grid_256(2, gemm_gm);
    dim3 gemm_grid_128(1, gemm_gm);

    const int spmm_blocks = (N_NODES * 32 + 255) / 256;   // warp per row
    const int split_blocks = (M * 64 + 255) / 256;

    // Layer 1: aspA = split(x); tmp = aspA @ W1'; aspB = split(relu-less... b1+spmm)
    split_w<<<(256 * 256 + 255) / 256, 256>>>(W1, wsp, 256);
    split_act<<<split_blocks, 256>>>(x, aspA, M);
    gemm_mma<<<gemm_grid_256, 256>>>(aspA, wsp, tmp, M, 256);
    csr_spmm_kernel<256, 1><<<spmm_blocks, 256>>>(tmp, val_s, col_s, rowptr, b1, aspB);

    // Layer 2: tmp = aspB @ W2'; aspA = split(relu(b2 + spmm))
    split_w<<<(256 * 256 + 255) / 256, 256>>>(W2, wsp, 256);
    gemm_mma<<<gemm_grid_256, 256>>>(aspB, wsp, tmp, M, 256);
    csr_spmm_kernel<256, 1><<<spmm_blocks, 256>>>(tmp, val_s, col_s, rowptr, b2, aspA);

    // Layer 3: tmp = aspA @ W3'; out = b3 + spmm  (fp32)
    split_w<<<(128 * 256 + 255) / 256, 256>>>(W3, wsp, 128);
    gemm_mma<<<gemm_grid_128, 256>>>(aspA, wsp, tmp, M, 128);
    csr_spmm_kernel<128, 0><<<spmm_blocks, 256>>>(tmp, val_s, col_s, rowptr, b3, out);
}